// round 11
// baseline (speedup 1.0000x reference)
#include <cuda_runtime.h>
#include <math.h>
#include <stdint.h>

// SparseMoEGate via mma.sync (HMMA) fp16x2 exact-split GEMM (3 MMAs/k-step).
// R11 = R10 + intra-stage register double-buffering: prefetch next k-step's
// x (LDS) and w (ldmatrix) during current k-step's MMAs; split after issue.
// x[16384,4096] f32, w[64,4096] f32
// out: [topk_idx as f32 (2T)] [topk_weight (2T)] [aux_loss (1)]

#define T_TOKENS 16384
#define C_DIM    4096
#define E_EXP    64
#define ALPHA    0.01f
#define WSCALE   16384.0f
#define WDESC    6.103515625e-05f   // 2^-14

#define BT    128             // tokens per CTA
#define NTH   512             // 16 warps
#define NKS   (C_DIM / 16)    // 256 k-steps
#define KPS   4               // k-steps per stage
#define NST   (NKS / KPS)     // 64 stages

#define XROW  272             // bytes per x row in smem (256B data + 16B pad)
#define XOFF_W 34816          // 128 * 272
#define WSTG  16384           // w bytes per stage (4 ksteps x 4KB)
#define SLOT  (XOFF_W + WSTG) // 51200
#define SMEM_BYTES (3 * SLOT) // 153600

__device__ float g_ssum[E_EXP];
__device__ float g_cnt[E_EXP];
__device__ unsigned g_done;
// B tiles, ldmatrix layout: [ks][nt][pl][t][n-row] 16B rows  (1 MB)
__device__ __align__(16) uint32_t w_frag[NKS * 1024];

// exact 2-way fp16 split of (even,odd) f32 pair -> 2 packed f16x2 (lo=even)
__device__ __forceinline__ void split2v(float fe, float fo,
                                        uint32_t& h1, uint32_t& h2) {
    asm("cvt.rn.f16x2.f32 %0, %1, %2;" : "=r"(h1) : "f"(fo), "f"(fe));
    float ge, go;
    asm("{ .reg .f16 l, h; mov.b32 {l, h}, %2;"
        " cvt.f32.f16 %0, l; cvt.f32.f16 %1, h; }"
        : "=f"(ge), "=f"(go) : "r"(h1));
    asm("cvt.rn.f16x2.f32 %0, %1, %2;" : "=r"(h2) : "f"(fo - go), "f"(fe - ge));
}

#define MMA(acc, A, B)                                                        \
    asm volatile(                                                             \
        "mma.sync.aligned.m16n8k16.row.col.f32.f16.f16.f32 "                  \
        "{%0,%1,%2,%3}, {%4,%5,%6,%7}, {%8,%9}, {%0,%1,%2,%3};"               \
        : "+f"(acc[0]), "+f"(acc[1]), "+f"(acc[2]), "+f"(acc[3])              \
        : "r"(A[0]), "r"(A[1]), "r"(A[2]), "r"(A[3]), "r"(B.x), "r"(B.y))

#define LDMX4(r0, r1, r2, r3, a)                                              \
    asm volatile("ldmatrix.sync.aligned.m8n8.x4.shared.b16 {%0,%1,%2,%3}, [%4];" \
        : "=r"(r0), "=r"(r1), "=r"(r2), "=r"(r3) : "r"(a))

__device__ __forceinline__ void cp16(uint32_t sa, const void* g) {
    asm volatile("cp.async.cg.shared.global [%0], [%1], 16;" :: "r"(sa), "l"(g));
}
__device__ __forceinline__ uint32_t smem_u32(const void* p) {
    uint32_t a;
    asm("{ .reg .u64 t; cvta.to.shared.u64 t, %1; cvt.u32.u64 %0, t; }"
        : "=r"(a) : "l"(p));
    return a;
}

// Precompute w fp16x2 planes (scaled by 2^14) in ldmatrix tile layout.
__global__ void prep_w(const float* __restrict__ w) {
    if (blockIdx.x == 0) {
        if (threadIdx.x < E_EXP) {
            g_ssum[threadIdx.x] = 0.f;
            g_cnt[threadIdx.x] = 0.f;
        }
        if (threadIdx.x == 64) g_done = 0;
    }
    int i = blockIdx.x * blockDim.x + threadIdx.x;   // 32768 threads
    int t = i & 1, e = (i >> 1) & 63, ks = i >> 7;
    const float* src = w + (size_t)e * C_DIM + ks * 16 + t * 8;
    uint32_t h1[4], h2[4];
    #pragma unroll
    for (int p = 0; p < 4; p++)
        split2v(src[2 * p] * WSCALE, src[2 * p + 1] * WSCALE, h1[p], h2[p]);
    int nt = e >> 3, n = e & 7;
    char* base = (char*)w_frag + (size_t)ks * 4096 + nt * 512 + t * 128 + n * 16;
    *(uint4*)(base)       = make_uint4(h1[0], h1[1], h1[2], h1[3]);  // plane 1
    *(uint4*)(base + 256) = make_uint4(h2[0], h2[1], h2[2], h2[3]);  // plane 2
}

extern __shared__ __align__(16) char dsm[];

__global__ __launch_bounds__(NTH) void gate_kernel(
    const float* __restrict__ x, float* __restrict__ out)
{
    __shared__ int s_cnt[E_EXP];
    __shared__ int s_last;
    float* lg = (float*)dsm;                 // epilogue overlay [BT][65]

    const int tid = threadIdx.x, blk = blockIdx.x;
    const int wid = tid >> 5, lane = tid & 31;
    const int tg = wid & 7;                  // token group (16 tokens)
    const int nh = wid >> 3;                 // expert half (32 experts)
    const int qr = lane >> 2, qc = lane & 3;
    const uint32_t sb = smem_u32(dsm);

    const int xr_lo = tg * 16 + qr;
    const int xr_hi = xr_lo + 8;
    const uint32_t wlane = (nh * 4) * 512 + ((lane >> 3) * 128) + ((lane & 7) * 16);

    // cp geometry: x rows 512 thr -> 64 rows x 8 segs(16B)
    const int crow = tid >> 3, cseg = tid & 7;
    const float* xg = x + (size_t)(blk * BT + crow) * C_DIM + cseg * 4;

    if (tid < E_EXP) s_cnt[tid] = 0;

    float acc[4][4];
    #pragma unroll
    for (int j = 0; j < 4; j++)
        #pragma unroll
        for (int q = 0; q < 4; q++) acc[j][q] = 0.f;

    auto stage_cp = [&](int st, int slot) {
        const uint32_t base = sb + slot * SLOT;
        #pragma unroll
        for (int rh = 0; rh < 2; rh++)
            #pragma unroll
            for (int kh = 0; kh < 2; kh++)
                cp16(base + (crow + rh * 64) * XROW + kh * 128 + cseg * 16,
                     xg + (size_t)(rh * 64) * C_DIM + st * 64 + kh * 32);
        const char* wsrc = (const char*)w_frag + (size_t)st * WSTG + tid * 16;
        cp16(base + XOFF_W + tid * 16, wsrc);
        cp16(base + XOFF_W + 8192 + tid * 16, wsrc + 8192);
    };

    stage_cp(0, 0); asm volatile("cp.async.commit_group;");
    stage_cp(1, 1); asm volatile("cp.async.commit_group;");

    #pragma unroll 1
    for (int i = 0; i < NST; i++) {
        asm volatile("cp.async.wait_group 1;");
        __syncthreads();                     // stage i visible; slot (i+2)%3 free

        if (i + 2 < NST) stage_cp(i + 2, (i + 2) % 3);
        asm volatile("cp.async.commit_group;");

        const char* xs = dsm + (i % 3) * SLOT;
        const uint32_t wbase = sb + (i % 3) * SLOT + XOFF_W + wlane;

        // ---- preload k-step 0 ----
        float2 px0 = *(const float2*)(xs + xr_lo * XROW + qc * 8);
        float2 px1 = *(const float2*)(xs + xr_hi * XROW + qc * 8);
        float2 px2 = *(const float2*)(xs + xr_lo * XROW + 32 + qc * 8);
        float2 px3 = *(const float2*)(xs + xr_hi * XROW + 32 + qc * 8);
        uint2 b1[4], b2[4];
        #pragma unroll
        for (int j = 0; j < 4; j++) {
            uint32_t r0, r1, r2, r3;
            LDMX4(r0, r1, r2, r3, wbase + j * 512);
            b1[j].x = r0; b1[j].y = r1;
            b2[j].x = r2; b2[j].y = r3;
        }
        uint32_t a1[4], a2[4];
        split2v(px0.x, px0.y, a1[0], a2[0]);
        split2v(px1.x, px1.y, a1[1], a2[1]);
        split2v(px2.x, px2.y, a1[2], a2[2]);
        split2v(px3.x, px3.y, a1[3], a2[3]);

        #pragma unroll
        for (int kk = 0; kk < KPS; kk++) {
            // prefetch next k-step (LDS + ldmatrix) before issuing MMAs
            float2 nx0, nx1, nx2, nx3;
            uint2 nb1[4], nb2[4];
            if (kk + 1 < KPS) {
                const int ko = (kk + 1) * 64;
                nx0 = *(const float2*)(xs + xr_lo * XROW + ko + qc * 8);
                nx1 = *(const float2*)(xs + xr_hi * XROW + ko + qc * 8);
                nx2 = *(const float2*)(xs + xr_lo * XROW + ko + 32 + qc * 8);
                nx3 = *(const float2*)(xs + xr_hi * XROW + ko + 32 + qc * 8);
                #pragma unroll
                for (int j = 0; j < 4; j++) {
                    uint32_t r0, r1, r2, r3;
                    LDMX4(r0, r1, r2, r3, wbase + (kk + 1) * 4096 + j * 512);
                    nb1[j].x = r0; nb1[j].y = r1;
                    nb2[j].x = r2; nb2[j].y = r3;
                }
            }

            // MMAs for current k-step (a/b resident in regs)
            #pragma unroll
            for (int j = 0; j < 4; j++) MMA(acc[j], a1, b1[j]);
            #pragma unroll
            for (int j = 0; j < 4; j++) MMA(acc[j], a2, b1[j]);
            #pragma unroll
            for (int j = 0; j < 4; j++) MMA(acc[j], a1, b2[j]);

            // split for next k-step overlaps tensor-pipe execution
            if (kk + 1 < KPS) {
                split2v(nx0.x, nx0.y, a1[0], a2[0]);
                split2v(nx1.x, nx1.y, a1[1], a2[1]);
                split2v(nx2.x, nx2.y, a1[2], a2[2]);
                split2v(nx3.x, nx3.y, a1[3], a2[3]);
                #pragma unroll
                for (int j = 0; j < 4; j++) { b1[j] = nb1[j]; b2[j] = nb2[j]; }
            }
        }
    }
    __syncthreads();    // staging done; reuse dsm as logits

    // scatter logits (descaled): row = tg*16 + qr (+8), col = (nh*4+j)*8 + 2*qc
    const int lr0 = tg * 16 + qr;
    #pragma unroll
    for (int j = 0; j < 4; j++) {
        const int e = (nh * 4 + j) * 8 + 2 * qc;
        lg[lr0 * 65 + e]           = acc[j][0] * WDESC;
        lg[lr0 * 65 + e + 1]       = acc[j][1] * WDESC;
        lg[(lr0 + 8) * 65 + e]     = acc[j][2] * WDESC;
        lg[(lr0 + 8) * 65 + e + 1] = acc[j][3] * WDESC;
    }
    __syncthreads();

    if (tid < BT) {
        float* row = lg + tid * 65;
        float v1 = -1e30f, v2 = -1e30f;
        int i1 = 0, i2 = 0;
        #pragma unroll
        for (int e = 0; e < E_EXP; e++) {
            float v = row[e];
            if (v > v1)      { v2 = v1; i2 = i1; v1 = v; i1 = e; }
            else if (v > v2) { v2 = v;  i2 = e; }
        }
        float Z = 0.f;
        #pragma unroll
        for (int e = 0; e < E_EXP; e++) {
            float ex = expf(row[e] - v1);
            row[e] = ex; Z += ex;
        }
        float rz = 1.0f / Z;
        #pragma unroll
        for (int e = 0; e < E_EXP; e++) row[e] *= rz;
        float s1 = row[i1], s2 = row[i2];
        float inv = 1.0f / (s1 + s2);
        int gt = blk * BT + tid;
        out[2 * gt]     = (float)i1;
        out[2 * gt + 1] = (float)i2;
        out[2 * T_TOKENS + 2 * gt]     = s1 * inv;
        out[2 * T_TOKENS + 2 * gt + 1] = s2 * inv;
        atomicAdd(&s_cnt[i1], 1);
        atomicAdd(&s_cnt[i2], 1);
    }
    __syncthreads();

    if (tid < E_EXP) {
        float sum = 0.f;
        for (int t = 0; t < BT; t++) sum += lg[t * 65 + tid];
        atomicAdd(&g_ssum[tid], sum);
        atomicAdd(&g_cnt[tid], (float)s_cnt[tid]);
    }
    __syncthreads();

    // last CTA computes aux loss
    if (tid == 0) {
        __threadfence();
        s_last = (atomicAdd(&g_done, 1u) == gridDim.x - 1);
    }
    __syncthreads();
    if (s_last) {
        if (tid < E_EXP) lg[tid] = g_ssum[tid] * g_cnt[tid];
        __syncthreads();
        if (tid == 0) {
            float s = 0.f;
            for (int e = 0; e < E_EXP; e++) s += lg[e];
            out[4 * T_TOKENS] = s * (ALPHA * (float)E_EXP /
                ((float)T_TOKENS * 2.0f * (float)T_TOKENS));
        }
    }
}

extern "C" void kernel_launch(void* const* d_in, const int* in_sizes, int n_in,
                              void* d_out, int out_size) {
    const float* x = (const float*)d_in[0];
    const float* w = (const float*)d_in[1];
    float* out = (float*)d_out;
    cudaFuncSetAttribute(gate_kernel,
                         cudaFuncAttributeMaxDynamicSharedMemorySize, SMEM_BYTES);
    prep_w<<<128, 256>>>(w);
    gate_kernel<<<T_TOKENS / BT, NTH, SMEM_BYTES>>>(x, out);
}